// round 2
// baseline (speedup 1.0000x reference)
#include <cuda_runtime.h>
#include <cstddef>

#define B_ 256
#define S_ 200
#define E_ 512
#define H_ 512

// ---- scratch (no allocations allowed) ----
__device__ float g_P[(size_t)B_ * S_ * H_];   // 104 MB: P[b*S+t][h] = x_t*Wxh + bxh + bhh
__device__ float g_h[2][B_ * H_];             // double-buffered hidden state
__device__ float g_pool[B_ * H_];             // time-mean of h
__device__ unsigned int g_bar;                // grid barrier counter

typedef unsigned long long u64;

__device__ __forceinline__ void fma2(u64 &c, u64 a, u64 b) {
    asm("fma.rn.f32x2 %0, %1, %2, %3;" : "=l"(c) : "l"(a), "l"(b), "l"(c));
}
__device__ __forceinline__ u64 splat2(float a) {
    u64 r; asm("mov.b64 %0, {%1, %1};" : "=l"(r) : "f"(a)); return r;
}
__device__ __forceinline__ float2 u2f(u64 v) {
    float2 r; asm("mov.b64 {%0, %1}, %2;" : "=f"(r.x), "=f"(r.y) : "l"(v)); return r;
}

// ============================================================================
// Kernel A: P[bt][n] = emb[x[bt]] @ Wxh + (bxh + bhh)
// GEMM M=51200 (gathered rows), N=512, K=512. Tile 64x64, 256 threads.
// ============================================================================
__global__ __launch_bounds__(256) void precompute_kernel(
    const int* __restrict__ x, const float* __restrict__ emb,
    const float* __restrict__ Wxh, const float* __restrict__ bxh,
    const float* __restrict__ bhh)
{
    __shared__ float As[16][64];   // [k][row]
    __shared__ float Wsm[16][64];  // [k][col]
    __shared__ int idx[64];

    const int n0 = blockIdx.x * 64;
    const int m0 = blockIdx.y * 64;
    const int t  = threadIdx.x;

    if (t < 64) idx[t] = x[m0 + t];
    __syncthreads();

    const int w = t >> 5, l = t & 31;
    const int half = l >> 4, ll = l & 15;
    const int row0 = w * 8 + half * 4;        // this thread: rows row0..row0+3
    const int c0 = 2 * ll, c1 = 2 * ll + 32;  // two column pairs

    const int arow = t >> 2, ak4 = (t & 3) * 4;   // A-tile load mapping
    const int krow = t >> 4, wc4 = (t & 15) * 4;  // W-tile load mapping
    const size_t embBase = (size_t)idx[arow] * E_;

    u64 acc[4][2];
#pragma unroll
    for (int i = 0; i < 4; i++) { acc[i][0] = 0ull; acc[i][1] = 0ull; }

    for (int kc = 0; kc < E_; kc += 16) {
        float4 av = *(const float4*)&emb[embBase + kc + ak4];
        float4 wv = *(const float4*)&Wxh[(size_t)(kc + krow) * H_ + n0 + wc4];
        __syncthreads();  // previous compute done before overwriting smem
        As[ak4 + 0][arow] = av.x; As[ak4 + 1][arow] = av.y;
        As[ak4 + 2][arow] = av.z; As[ak4 + 3][arow] = av.w;
        *(float4*)&Wsm[krow][wc4] = wv;
        __syncthreads();
#pragma unroll
        for (int k = 0; k < 16; k++) {
            u64 w0 = *(const u64*)&Wsm[k][c0];
            u64 w1 = *(const u64*)&Wsm[k][c1];
#pragma unroll
            for (int i = 0; i < 4; i++) {
                u64 aa = splat2(As[k][row0 + i]);
                fma2(acc[i][0], aa, w0);
                fma2(acc[i][1], aa, w1);
            }
        }
    }

    float2 b0, b1;
    b0.x = bxh[n0 + c0]     + bhh[n0 + c0];
    b0.y = bxh[n0 + c0 + 1] + bhh[n0 + c0 + 1];
    b1.x = bxh[n0 + c1]     + bhh[n0 + c1];
    b1.y = bxh[n0 + c1 + 1] + bhh[n0 + c1 + 1];
#pragma unroll
    for (int i = 0; i < 4; i++) {
        float2 v0 = u2f(acc[i][0]); v0.x += b0.x; v0.y += b0.y;
        float2 v1 = u2f(acc[i][1]); v1.x += b1.x; v1.y += b1.y;
        size_t r = (size_t)(m0 + row0 + i) * H_ + n0;
        *(float2*)&g_P[r + c0] = v0;
        *(float2*)&g_P[r + c1] = v1;
    }
}

// ============================================================================
// Kernel B: persistent recurrent kernel.
// 128 CTAs (16 M-tiles x 8 N-tiles). Whh N-slice resident in smem (128 KB).
// Per step: h_new = relu(P[:,t,:] + h @ Whh); one grid barrier per step.
// ============================================================================
#define ASTRIDE 516
#define RNN_SMEM ((H_ * 64 + 16 * ASTRIDE) * 4)  // 131072 + 33024 = 164096 B

__device__ __forceinline__ void grid_bar(int t, unsigned target) {
    __syncthreads();
    if (t == 0) {
        unsigned* bp = &g_bar;
        asm volatile("red.release.gpu.add.u32 [%0], 1;" :: "l"(bp) : "memory");
        unsigned v;
        do {
            asm volatile("ld.acquire.gpu.u32 %0, [%1];" : "=r"(v) : "l"(bp) : "memory");
        } while (v < target);
    }
    __syncthreads();
}

#define RSTEP(a0v, a1v, kk) {                          \
    u64 w0 = *(const u64*)&Ws[(kk) * 64 + c0];         \
    u64 w1 = *(const u64*)&Ws[(kk) * 64 + c1];         \
    u64 s0 = splat2(a0v);                              \
    u64 s1 = splat2(a1v);                              \
    fma2(acc00, s0, w0); fma2(acc01, s0, w1);          \
    fma2(acc10, s1, w0); fma2(acc11, s1, w1); }

__global__ __launch_bounds__(128, 1) void rnn_kernel(const float* __restrict__ Whh)
{
    extern __shared__ float sm[];
    float* Ws = sm;               // [512][64] Whh slice (stationary)
    float* As = sm + H_ * 64;     // [16][ASTRIDE] current h rows

    const int cta = blockIdx.x;
    const int m0 = (cta >> 3) * 16;
    const int n0 = (cta & 7) * 64;
    const int t = threadIdx.x;
    const int w = t >> 5, l = t & 31;
    const int half = l >> 4, ll = l & 15;
    const int r0 = w * 4 + half * 2;   // rows r0, r0+1 of the 16-row tile
    const int r1 = r0 + 1;
    const int c0 = 2 * ll, c1 = 2 * ll + 32;

    // Load Whh[:, n0:n0+64] into smem once.
#pragma unroll 4
    for (int rep = 0; rep < 64; rep++) {
        int i4 = rep * 128 + t;
        int k  = i4 >> 4;
        int j4 = (i4 & 15) * 4;
        *(float4*)&Ws[k * 64 + j4] = *(const float4*)&Whh[(size_t)k * H_ + n0 + j4];
    }

    float hs00x = 0, hs00y = 0, hs01x = 0, hs01y = 0;
    float hs10x = 0, hs10y = 0, hs11x = 0, hs11y = 0;

    int cur = 0;
    for (int step = 0; step < S_; step++) {
        const float* hsrc = g_h[cur];
#pragma unroll
        for (int rep = 0; rep < 16; rep++) {
            int i4  = rep * 128 + t;
            int row = i4 >> 7;
            int k4  = (i4 & 127) * 4;
            *(float4*)&As[row * ASTRIDE + k4] =
                *(const float4*)&hsrc[(size_t)(m0 + row) * H_ + k4];
        }
        __syncthreads();  // also covers first-use of Ws

        size_t p0 = ((size_t)(m0 + r0) * S_ + step) * H_ + n0;
        size_t p1 = ((size_t)(m0 + r1) * S_ + step) * H_ + n0;
        u64 acc00 = *(const u64*)&g_P[p0 + c0];
        u64 acc01 = *(const u64*)&g_P[p0 + c1];
        u64 acc10 = *(const u64*)&g_P[p1 + c0];
        u64 acc11 = *(const u64*)&g_P[p1 + c1];

        const float* a0p = &As[r0 * ASTRIDE];
        const float* a1p = &As[r1 * ASTRIDE];
#pragma unroll 2
        for (int k = 0; k < H_; k += 4) {
            float4 A0 = *(const float4*)(a0p + k);
            float4 A1 = *(const float4*)(a1p + k);
            RSTEP(A0.x, A1.x, k + 0);
            RSTEP(A0.y, A1.y, k + 1);
            RSTEP(A0.z, A1.z, k + 2);
            RSTEP(A0.w, A1.w, k + 3);
        }

        float* hdst = g_h[cur ^ 1];
        size_t o0 = (size_t)(m0 + r0) * H_ + n0;
        size_t o1 = (size_t)(m0 + r1) * H_ + n0;
        float2 v;
        v = u2f(acc00); v.x = fmaxf(v.x, 0.f); v.y = fmaxf(v.y, 0.f);
        *(float2*)&hdst[o0 + c0] = v; hs00x += v.x; hs00y += v.y;
        v = u2f(acc01); v.x = fmaxf(v.x, 0.f); v.y = fmaxf(v.y, 0.f);
        *(float2*)&hdst[o0 + c1] = v; hs01x += v.x; hs01y += v.y;
        v = u2f(acc10); v.x = fmaxf(v.x, 0.f); v.y = fmaxf(v.y, 0.f);
        *(float2*)&hdst[o1 + c0] = v; hs10x += v.x; hs10y += v.y;
        v = u2f(acc11); v.x = fmaxf(v.x, 0.f); v.y = fmaxf(v.y, 0.f);
        *(float2*)&hdst[o1 + c1] = v; hs11x += v.x; hs11y += v.y;

        grid_bar(t, 128u * (unsigned)(step + 1));
        cur ^= 1;
    }

    const float inv = 1.0f / (float)S_;
    size_t o0 = (size_t)(m0 + r0) * H_ + n0;
    size_t o1 = (size_t)(m0 + r1) * H_ + n0;
    float2 q;
    q.x = hs00x * inv; q.y = hs00y * inv; *(float2*)&g_pool[o0 + c0] = q;
    q.x = hs01x * inv; q.y = hs01y * inv; *(float2*)&g_pool[o0 + c1] = q;
    q.x = hs10x * inv; q.y = hs10y * inv; *(float2*)&g_pool[o1 + c0] = q;
    q.x = hs11x * inv; q.y = hs11y * inv; *(float2*)&g_pool[o1 + c1] = q;
}

// ============================================================================
// Kernel C: out[b][j] = pooled[b] @ Wfc[:,j] + bfc[j]
// ============================================================================
__global__ __launch_bounds__(128) void fc_kernel(const float* __restrict__ Wfc,
                                                 const float* __restrict__ bfc,
                                                 float* __restrict__ out)
{
    const int b = blockIdx.x;
    const int t = threadIdx.x;
    float s0 = 0, s1 = 0, s2 = 0, s3 = 0;
    const float* pr = &g_pool[(size_t)b * H_];
    for (int k = t; k < H_; k += 128) {
        float v = pr[k];
        float4 wv = *(const float4*)&Wfc[k * 4];
        s0 += v * wv.x; s1 += v * wv.y; s2 += v * wv.z; s3 += v * wv.w;
    }
#pragma unroll
    for (int o = 16; o > 0; o >>= 1) {
        s0 += __shfl_down_sync(0xffffffffu, s0, o);
        s1 += __shfl_down_sync(0xffffffffu, s1, o);
        s2 += __shfl_down_sync(0xffffffffu, s2, o);
        s3 += __shfl_down_sync(0xffffffffu, s3, o);
    }
    __shared__ float red[4][4];
    if ((t & 31) == 0) {
        int wrp = t >> 5;
        red[wrp][0] = s0; red[wrp][1] = s1; red[wrp][2] = s2; red[wrp][3] = s3;
    }
    __syncthreads();
    if (t < 4) {
        out[b * 4 + t] = red[0][t] + red[1][t] + red[2][t] + red[3][t] + bfc[t];
    }
}

// ============================================================================
extern "C" void kernel_launch(void* const* d_in, const int* in_sizes, int n_in,
                              void* d_out, int out_size)
{
    const int*   x   = (const int*)d_in[0];
    const float* emb = (const float*)d_in[1];
    const float* Wxh = (const float*)d_in[2];
    const float* bxh = (const float*)d_in[3];
    const float* Whh = (const float*)d_in[4];
    const float* bhh = (const float*)d_in[5];
    const float* Wfc = (const float*)d_in[6];
    const float* bfc = (const float*)d_in[7];
    float* out = (float*)d_out;

    void *hAddr = nullptr, *barAddr = nullptr;
    cudaGetSymbolAddress(&hAddr, g_h);
    cudaGetSymbolAddress(&barAddr, g_bar);
    cudaMemsetAsync(hAddr, 0, sizeof(float) * 2 * B_ * H_);
    cudaMemsetAsync(barAddr, 0, sizeof(unsigned));

    cudaFuncSetAttribute(rnn_kernel, cudaFuncAttributeMaxDynamicSharedMemorySize, RNN_SMEM);

    precompute_kernel<<<dim3(8, (B_ * S_) / 64), 256>>>(x, emb, Wxh, bxh, bhh);
    rnn_kernel<<<128, 128, RNN_SMEM>>>(Whh);
    fc_kernel<<<B_, 128>>>(Wfc, bfc, out);
}

// round 3
// speedup vs baseline: 1.1525x; 1.1525x over previous
#include <cuda_runtime.h>
#include <cstddef>

#define B_ 256
#define S_ 200
#define E_ 512
#define H_ 512

// ---- scratch (no allocations allowed) ----
__device__ float g_P[(size_t)B_ * S_ * H_];   // 104 MB: P[t][b][h] = x_t*Wxh + bxh + bhh
__device__ float g_h[2][B_ * H_];             // double-buffered hidden state
__device__ float g_pool[B_ * H_];             // time-mean of h
__device__ unsigned int g_bars[16];           // per-M-group barrier counters

typedef unsigned long long u64;

__device__ __forceinline__ void fma2(u64 &c, u64 a, u64 b) {
    asm("fma.rn.f32x2 %0, %1, %2, %3;" : "=l"(c) : "l"(a), "l"(b), "l"(c));
}
__device__ __forceinline__ u64 splat2(float a) {
    u64 r; asm("mov.b64 %0, {%1, %1};" : "=l"(r) : "f"(a)); return r;
}
__device__ __forceinline__ float2 u2f(u64 v) {
    float2 r; asm("mov.b64 {%0, %1}, %2;" : "=f"(r.x), "=f"(r.y) : "l"(v)); return r;
}

// ============================================================================
// Kernel A: P[t][b][:] = emb[x[b,t]] @ Wxh + (bxh + bhh)
// GEMM M=51200 (gathered rows), N=512, K=512. Tile 64x64, 256 threads (8 warps).
// Warp w owns rows 8w..8w+7; lane l owns columns 2l, 2l+1 (one f32x2).
// Per 4k per thread: 8 broadcast LDS.128 (A) + 4 LDS.64 (W) + 32 FFMA2.
// ============================================================================
#define AST 36  // As row stride (32 + 4 pad)

__global__ __launch_bounds__(256) void precompute_kernel(
    const int* __restrict__ x, const float* __restrict__ emb,
    const float* __restrict__ Wxh, const float* __restrict__ bxh,
    const float* __restrict__ bhh)
{
    __shared__ float As[64 * AST];   // [row][k]  (k-chunk = 32)
    __shared__ float Ws[32 * 64];    // [k][col]
    __shared__ int idx[64];

    const int n0 = blockIdx.x * 64;
    const int m0 = blockIdx.y * 64;
    const int t  = threadIdx.x;

    if (t < 64) idx[t] = x[m0 + t];
    __syncthreads();

    const int w = t >> 5, l = t & 31;
    const int row0 = w * 8;
    const int c = 2 * l;

    // load mappings (2 reps each: A 512 float4, W 512 float4, 256 threads)
    const int arow = t >> 3, ak4 = (t & 7) * 4;     // A: rows arow, arow+32
    const int wrow = t >> 4, wc4 = (t & 15) * 4;    // W: k rows wrow, wrow+16
    const size_t e0 = (size_t)idx[arow] * E_;
    const size_t e1 = (size_t)idx[arow + 32] * E_;

    u64 acc0 = 0, acc1 = 0, acc2 = 0, acc3 = 0;
    u64 acc4 = 0, acc5 = 0, acc6 = 0, acc7 = 0;

    for (int kc = 0; kc < E_; kc += 32) {
        float4 av0 = *(const float4*)&emb[e0 + kc + ak4];
        float4 av1 = *(const float4*)&emb[e1 + kc + ak4];
        float4 wv0 = *(const float4*)&Wxh[(size_t)(kc + wrow) * H_ + n0 + wc4];
        float4 wv1 = *(const float4*)&Wxh[(size_t)(kc + wrow + 16) * H_ + n0 + wc4];
        __syncthreads();
        *(float4*)&As[arow * AST + ak4]        = av0;
        *(float4*)&As[(arow + 32) * AST + ak4] = av1;
        *(float4*)&Ws[wrow * 64 + wc4]         = wv0;
        *(float4*)&Ws[(wrow + 16) * 64 + wc4]  = wv1;
        __syncthreads();

#pragma unroll
        for (int k = 0; k < 32; k += 4) {
            float4 A0 = *(const float4*)&As[(row0 + 0) * AST + k];
            float4 A1 = *(const float4*)&As[(row0 + 1) * AST + k];
            float4 A2 = *(const float4*)&As[(row0 + 2) * AST + k];
            float4 A3 = *(const float4*)&As[(row0 + 3) * AST + k];
            float4 A4 = *(const float4*)&As[(row0 + 4) * AST + k];
            float4 A5 = *(const float4*)&As[(row0 + 5) * AST + k];
            float4 A6 = *(const float4*)&As[(row0 + 6) * AST + k];
            float4 A7 = *(const float4*)&As[(row0 + 7) * AST + k];
            const float* wp = &Ws[k * 64 + c];
#define PK(comp) {                                          \
            u64 wv = *(const u64*)(wp); wp += 64;           \
            fma2(acc0, splat2(A0.comp), wv);                \
            fma2(acc1, splat2(A1.comp), wv);                \
            fma2(acc2, splat2(A2.comp), wv);                \
            fma2(acc3, splat2(A3.comp), wv);                \
            fma2(acc4, splat2(A4.comp), wv);                \
            fma2(acc5, splat2(A5.comp), wv);                \
            fma2(acc6, splat2(A6.comp), wv);                \
            fma2(acc7, splat2(A7.comp), wv); }
            PK(x) PK(y) PK(z) PK(w)
#undef PK
        }
    }

    const float bx0 = bxh[n0 + c]     + bhh[n0 + c];
    const float bx1 = bxh[n0 + c + 1] + bhh[n0 + c + 1];
    u64 accs[8] = {acc0, acc1, acc2, acc3, acc4, acc5, acc6, acc7};
#pragma unroll
    for (int i = 0; i < 8; i++) {
        float2 v = u2f(accs[i]); v.x += bx0; v.y += bx1;
        int m = m0 + row0 + i;
        int bb = m / S_;
        int tt = m - bb * S_;
        *(float2*)&g_P[((size_t)tt * B_ + bb) * H_ + n0 + c] = v;
    }
}

// ============================================================================
// Kernel B: persistent recurrent kernel.
// 128 CTAs = 16 M-groups x 8 N-tiles. Whh N-slice resident in smem (128 KB).
// Warp w owns rows 4w..4w+3; lane l owns columns 2l, 2l+1 (one f32x2).
// Per-M-group barrier (8 CTAs) instead of grid-wide.
// ============================================================================
#define ASTRIDE 516
#define RNN_SMEM ((H_ * 64 + 16 * ASTRIDE) * 4)  // 131072 + 33024 = 164096 B

#define RK(comp) {                                   \
    u64 wv = *(const u64*)(wp); wp += 64;            \
    fma2(a0, splat2(A0.comp), wv);                   \
    fma2(a1, splat2(A1.comp), wv);                   \
    fma2(a2, splat2(A2.comp), wv);                   \
    fma2(a3, splat2(A3.comp), wv); }

__global__ __launch_bounds__(128, 1) void rnn_kernel(const float* __restrict__ Whh)
{
    extern __shared__ float sm[];
    float* Ws = sm;               // [512][64] Whh slice (stationary)
    float* As = sm + H_ * 64;     // [16][ASTRIDE] current h rows

    const int cta = blockIdx.x;
    const int mg  = cta >> 3;          // M-group 0..15
    const int m0  = mg * 16;
    const int n0  = (cta & 7) * 64;
    const int t   = threadIdx.x;
    const int w   = t >> 5, l = t & 31;
    const int c   = 2 * l;
    const int r0  = 4 * w;             // rows r0..r0+3 of the 16-row tile

    // Load Whh[:, n0:n0+64] into smem once.
#pragma unroll 4
    for (int rep = 0; rep < 64; rep++) {
        int i4 = rep * 128 + t;
        int k  = i4 >> 4;
        int j4 = (i4 & 15) * 4;
        *(float4*)&Ws[k * 64 + j4] = *(const float4*)&Whh[(size_t)k * H_ + n0 + j4];
    }

    float2 ps0 = {0, 0}, ps1 = {0, 0}, ps2 = {0, 0}, ps3 = {0, 0};

    unsigned* bar = &g_bars[mg];
    int cur = 0;
    for (int step = 0; step < S_; step++) {
        const float* hsrc = g_h[cur];
#pragma unroll
        for (int rep = 0; rep < 16; rep++) {
            int i4  = rep * 128 + t;
            int row = i4 >> 7;
            int k4  = (i4 & 127) * 4;
            *(float4*)&As[row * ASTRIDE + k4] =
                *(const float4*)&hsrc[(size_t)(m0 + row) * H_ + k4];
        }
        __syncthreads();  // also covers first-use of Ws / prior-step As reads

        // acc init from P[t][b][h] (contiguous per step)
        const size_t pb = ((size_t)step * B_ + m0 + r0) * H_ + n0 + c;
        u64 a0 = *(const u64*)&g_P[pb];
        u64 a1 = *(const u64*)&g_P[pb + H_];
        u64 a2 = *(const u64*)&g_P[pb + 2 * H_];
        u64 a3 = *(const u64*)&g_P[pb + 3 * H_];

        const float* ap0 = &As[(r0 + 0) * ASTRIDE];
        const float* ap1 = &As[(r0 + 1) * ASTRIDE];
        const float* ap2 = &As[(r0 + 2) * ASTRIDE];
        const float* ap3 = &As[(r0 + 3) * ASTRIDE];
#pragma unroll 4
        for (int k = 0; k < H_; k += 4) {
            float4 A0 = *(const float4*)(ap0 + k);
            float4 A1 = *(const float4*)(ap1 + k);
            float4 A2 = *(const float4*)(ap2 + k);
            float4 A3 = *(const float4*)(ap3 + k);
            const float* wp = &Ws[k * 64 + c];
            RK(x) RK(y) RK(z) RK(w)
        }

        float* hdst = g_h[cur ^ 1];
        const size_t ob = (size_t)(m0 + r0) * H_ + n0 + c;
        float2 v;
        v = u2f(a0); v.x = fmaxf(v.x, 0.f); v.y = fmaxf(v.y, 0.f);
        *(float2*)&hdst[ob]          = v; ps0.x += v.x; ps0.y += v.y;
        v = u2f(a1); v.x = fmaxf(v.x, 0.f); v.y = fmaxf(v.y, 0.f);
        *(float2*)&hdst[ob + H_]     = v; ps1.x += v.x; ps1.y += v.y;
        v = u2f(a2); v.x = fmaxf(v.x, 0.f); v.y = fmaxf(v.y, 0.f);
        *(float2*)&hdst[ob + 2 * H_] = v; ps2.x += v.x; ps2.y += v.y;
        v = u2f(a3); v.x = fmaxf(v.x, 0.f); v.y = fmaxf(v.y, 0.f);
        *(float2*)&hdst[ob + 3 * H_] = v; ps3.x += v.x; ps3.y += v.y;

        // group barrier: only the 8 CTAs sharing this M-group must sync
        __syncthreads();
        if (t == 0) {
            asm volatile("red.release.gpu.add.u32 [%0], 1;" :: "l"(bar) : "memory");
            unsigned v8, target = 8u * (unsigned)(step + 1);
            do {
                asm volatile("ld.acquire.gpu.u32 %0, [%1];" : "=r"(v8) : "l"(bar) : "memory");
            } while (v8 < target);
        }
        __syncthreads();
        cur ^= 1;
    }

    const float inv = 1.0f / (float)S_;
    const size_t ob = (size_t)(m0 + r0) * H_ + n0 + c;
    float2 q;
    q.x = ps0.x * inv; q.y = ps0.y * inv; *(float2*)&g_pool[ob]          = q;
    q.x = ps1.x * inv; q.y = ps1.y * inv; *(float2*)&g_pool[ob + H_]     = q;
    q.x = ps2.x * inv; q.y = ps2.y * inv; *(float2*)&g_pool[ob + 2 * H_] = q;
    q.x = ps3.x * inv; q.y = ps3.y * inv; *(float2*)&g_pool[ob + 3 * H_] = q;
}

// ============================================================================
// Kernel C: out[b][j] = pooled[b] @ Wfc[:,j] + bfc[j]
// ============================================================================
__global__ __launch_bounds__(128) void fc_kernel(const float* __restrict__ Wfc,
                                                 const float* __restrict__ bfc,
                                                 float* __restrict__ out)
{
    const int b = blockIdx.x;
    const int t = threadIdx.x;
    float s0 = 0, s1 = 0, s2 = 0, s3 = 0;
    const float* pr = &g_pool[(size_t)b * H_];
    for (int k = t; k < H_; k += 128) {
        float v = pr[k];
        float4 wv = *(const float4*)&Wfc[k * 4];
        s0 += v * wv.x; s1 += v * wv.y; s2 += v * wv.z; s3 += v * wv.w;
    }
#pragma unroll
    for (int o = 16; o > 0; o >>= 1) {
        s0 += __shfl_down_sync(0xffffffffu, s0, o);
        s1 += __shfl_down_sync(0xffffffffu, s1, o);
        s2 += __shfl_down_sync(0xffffffffu, s2, o);
        s3 += __shfl_down_sync(0xffffffffu, s3, o);
    }
    __shared__ float red[4][4];
    if ((t & 31) == 0) {
        int wrp = t >> 5;
        red[wrp][0] = s0; red[wrp][1] = s1; red[wrp][2] = s2; red[wrp][3] = s3;
    }
    __syncthreads();
    if (t < 4) {
        out[b * 4 + t] = red[0][t] + red[1][t] + red[2][t] + red[3][t] + bfc[t];
    }
}

// ============================================================================
extern "C" void kernel_launch(void* const* d_in, const int* in_sizes, int n_in,
                              void* d_out, int out_size)
{
    const int*   x   = (const int*)d_in[0];
    const float* emb = (const float*)d_in[1];
    const float* Wxh = (const float*)d_in[2];
    const float* bxh = (const float*)d_in[3];
    const float* Whh = (const float*)d_in[4];
    const float* bhh = (const float*)d_in[5];
    const float* Wfc = (const float*)d_in[6];
    const float* bfc = (const float*)d_in[7];
    float* out = (float*)d_out;

    void *hAddr = nullptr, *barAddr = nullptr;
    cudaGetSymbolAddress(&hAddr, g_h);
    cudaGetSymbolAddress(&barAddr, g_bars);
    cudaMemsetAsync(hAddr, 0, sizeof(float) * 2 * B_ * H_);
    cudaMemsetAsync(barAddr, 0, sizeof(unsigned) * 16);

    cudaFuncSetAttribute(rnn_kernel, cudaFuncAttributeMaxDynamicSharedMemorySize, RNN_SMEM);

    precompute_kernel<<<dim3(8, (B_ * S_) / 64), 256>>>(x, emb, Wxh, bxh, bhh);
    rnn_kernel<<<128, 128, RNN_SMEM>>>(Whh);
    fc_kernel<<<B_, 128>>>(Wfc, bfc, out);
}

// round 5
// speedup vs baseline: 1.2427x; 1.0782x over previous
#include <cuda_runtime.h>
#include <cstddef>

#define B_ 256
#define S_ 200
#define E_ 512
#define H_ 512

// ---- scratch (no allocations allowed) ----
__device__ float g_P[(size_t)B_ * S_ * H_];   // 104 MB: P[t][b][h]
__device__ float g_h[2][B_ * H_];             // double-buffered hidden state
__device__ float g_pool[B_ * H_];             // time-mean of h
__device__ unsigned int g_bars[16];           // per-M-group barrier counters

typedef unsigned long long u64;

__device__ __forceinline__ void fma2(u64 &c, u64 a, u64 b) {
    asm("fma.rn.f32x2 %0, %1, %2, %3;" : "=l"(c) : "l"(a), "l"(b), "l"(c));
}
__device__ __forceinline__ u64 splat2(float a) {
    u64 r; asm("mov.b64 %0, {%1, %1};" : "=l"(r) : "f"(a)); return r;
}
__device__ __forceinline__ float2 u2f(u64 v) {
    float2 r; asm("mov.b64 {%0, %1}, %2;" : "=f"(r.x), "=f"(r.y) : "l"(v)); return r;
}

// ============================================================================
// Kernel A: P = gather(emb, x) @ Wxh + (bxh + bhh)
// GEMM M=51200, N=512, K=512. CTA tile 64x128, 256 threads (8 warps).
// Warp w: rows 8w..8w+7; lane l: cols 4l..4l+3 (two f32x2 accumulators/row).
// Double-buffered smem, k-chunk 32, register prefetch: ONE sync per chunk.
// ============================================================================
#define PAST 36  // A row stride (32 + 4 pad)
#define PC_SMEM ((2 * 64 * PAST + 2 * 32 * 128) * 4)  // 18432 + 32768 = 51200 B

__global__ __launch_bounds__(256, 2) void precompute_kernel(
    const int* __restrict__ x, const float* __restrict__ emb,
    const float* __restrict__ Wxh, const float* __restrict__ bxh,
    const float* __restrict__ bhh)
{
    extern __shared__ float psm[];
    float* AsB = psm;                    // [2][64][PAST]
    float* WsB = psm + 2 * 64 * PAST;    // [2][32][128]

    const int n0 = blockIdx.x * 128;
    const int m0 = blockIdx.y * 64;
    const int t  = threadIdx.x;
    const int w  = t >> 5, l = t & 31;
    const int row0 = w * 8;
    const int c4 = 4 * l;

    // A load mapping: thread covers rows (t>>3) and (t>>3)+32, k-slot (t&7)*4
    const int arow  = t >> 3;
    const int aslot = (t & 7) * 4;
    const size_t e0 = (size_t)x[m0 + arow] * E_;
    const size_t e1 = (size_t)x[m0 + arow + 32] * E_;
    // W load mapping: 4 reps, rep r covers k-row r*8 + (t>>5), col (t&31)*4
    const int wrow = t >> 5;
    const int wcol = (t & 31) * 4;

    u64 acc[8][2];
#pragma unroll
    for (int i = 0; i < 8; i++) { acc[i][0] = 0ull; acc[i][1] = 0ull; }

    float4 pa0, pa1, pw0, pw1, pw2, pw3;
    // prologue: load chunk 0
    pa0 = *(const float4*)&emb[e0 + aslot];
    pa1 = *(const float4*)&emb[e1 + aslot];
    pw0 = *(const float4*)&Wxh[(size_t)(0  + wrow) * H_ + n0 + wcol];
    pw1 = *(const float4*)&Wxh[(size_t)(8  + wrow) * H_ + n0 + wcol];
    pw2 = *(const float4*)&Wxh[(size_t)(16 + wrow) * H_ + n0 + wcol];
    pw3 = *(const float4*)&Wxh[(size_t)(24 + wrow) * H_ + n0 + wcol];
    *(float4*)&AsB[arow * PAST + aslot]        = pa0;
    *(float4*)&AsB[(arow + 32) * PAST + aslot] = pa1;
    *(float4*)&WsB[(0  + wrow) * 128 + wcol] = pw0;
    *(float4*)&WsB[(8  + wrow) * 128 + wcol] = pw1;
    *(float4*)&WsB[(16 + wrow) * 128 + wcol] = pw2;
    *(float4*)&WsB[(24 + wrow) * 128 + wcol] = pw3;
    __syncthreads();

#pragma unroll 1
    for (int ch = 0; ch < 16; ch++) {
        if (ch < 15) {
            const int kn = (ch + 1) * 32;
            pa0 = *(const float4*)&emb[e0 + kn + aslot];
            pa1 = *(const float4*)&emb[e1 + kn + aslot];
            pw0 = *(const float4*)&Wxh[(size_t)(kn + wrow) * H_ + n0 + wcol];
            pw1 = *(const float4*)&Wxh[(size_t)(kn + 8  + wrow) * H_ + n0 + wcol];
            pw2 = *(const float4*)&Wxh[(size_t)(kn + 16 + wrow) * H_ + n0 + wcol];
            pw3 = *(const float4*)&Wxh[(size_t)(kn + 24 + wrow) * H_ + n0 + wcol];
        }
        const float* Ab = AsB + (ch & 1) * (64 * PAST);
        const float* Wb = WsB + (ch & 1) * (32 * 128);

#pragma unroll
        for (int kg = 0; kg < 8; kg++) {
            float4 a0 = *(const float4*)&Ab[(row0 + 0) * PAST + kg * 4];
            float4 a1 = *(const float4*)&Ab[(row0 + 1) * PAST + kg * 4];
            float4 a2 = *(const float4*)&Ab[(row0 + 2) * PAST + kg * 4];
            float4 a3 = *(const float4*)&Ab[(row0 + 3) * PAST + kg * 4];
            float4 a4 = *(const float4*)&Ab[(row0 + 4) * PAST + kg * 4];
            float4 a5 = *(const float4*)&Ab[(row0 + 5) * PAST + kg * 4];
            float4 a6 = *(const float4*)&Ab[(row0 + 6) * PAST + kg * 4];
            float4 a7 = *(const float4*)&Ab[(row0 + 7) * PAST + kg * 4];
#define PKJ(j, comp) {                                              \
            const u64* wp = (const u64*)&Wb[(kg * 4 + (j)) * 128 + c4]; \
            u64 w01 = wp[0], w23 = wp[1];                           \
            fma2(acc[0][0], splat2(a0.comp), w01); fma2(acc[0][1], splat2(a0.comp), w23); \
            fma2(acc[1][0], splat2(a1.comp), w01); fma2(acc[1][1], splat2(a1.comp), w23); \
            fma2(acc[2][0], splat2(a2.comp), w01); fma2(acc[2][1], splat2(a2.comp), w23); \
            fma2(acc[3][0], splat2(a3.comp), w01); fma2(acc[3][1], splat2(a3.comp), w23); \
            fma2(acc[4][0], splat2(a4.comp), w01); fma2(acc[4][1], splat2(a4.comp), w23); \
            fma2(acc[5][0], splat2(a5.comp), w01); fma2(acc[5][1], splat2(a5.comp), w23); \
            fma2(acc[6][0], splat2(a6.comp), w01); fma2(acc[6][1], splat2(a6.comp), w23); \
            fma2(acc[7][0], splat2(a7.comp), w01); fma2(acc[7][1], splat2(a7.comp), w23); }
            PKJ(0, x) PKJ(1, y) PKJ(2, z) PKJ(3, w)
#undef PKJ
        }

        if (ch < 15) {
            float* An = AsB + ((ch + 1) & 1) * (64 * PAST);
            float* Wn = WsB + ((ch + 1) & 1) * (32 * 128);
            *(float4*)&An[arow * PAST + aslot]        = pa0;
            *(float4*)&An[(arow + 32) * PAST + aslot] = pa1;
            *(float4*)&Wn[(0  + wrow) * 128 + wcol] = pw0;
            *(float4*)&Wn[(8  + wrow) * 128 + wcol] = pw1;
            *(float4*)&Wn[(16 + wrow) * 128 + wcol] = pw2;
            *(float4*)&Wn[(24 + wrow) * 128 + wcol] = pw3;
            __syncthreads();
        }
    }

    float4 bxv = *(const float4*)&bxh[n0 + c4];
    float4 bhv = *(const float4*)&bhh[n0 + c4];
    const float b0 = bxv.x + bhv.x, b1 = bxv.y + bhv.y;
    const float b2 = bxv.z + bhv.z, b3 = bxv.w + bhv.w;
#pragma unroll
    for (int i = 0; i < 8; i++) {
        float2 v0 = u2f(acc[i][0]);
        float2 v1 = u2f(acc[i][1]);
        float4 o; o.x = v0.x + b0; o.y = v0.y + b1; o.z = v1.x + b2; o.w = v1.y + b3;
        int m = m0 + row0 + i;
        int bb = m / S_;
        int tt = m - bb * S_;
        *(float4*)&g_P[((size_t)tt * B_ + bb) * H_ + n0 + c4] = o;
    }
}

// ============================================================================
// Kernel B: persistent recurrent kernel.
// 128 CTAs = 16 M-groups x 8 N-tiles. Whh N-slice resident in smem (128 KB).
// Warp w: rows 4w..4w+3; lane l: cols 2l,2l+1. Per-M-group barrier (8 CTAs).
// P[t+1] register-prefetched before the barrier spin each step.
// ============================================================================
#define ASTRIDE 516
#define RNN_SMEM ((H_ * 64 + 16 * ASTRIDE) * 4)  // 164096 B

#define RK(comp) {                                   \
    u64 wv = *(const u64*)(wp); wp += 64;            \
    fma2(a0, splat2(A0.comp), wv);                   \
    fma2(a1, splat2(A1.comp), wv);                   \
    fma2(a2, splat2(A2.comp), wv);                   \
    fma2(a3, splat2(A3.comp), wv); }

__global__ __launch_bounds__(128, 1) void rnn_kernel(const float* __restrict__ Whh)
{
    extern __shared__ float sm[];
    float* Ws = sm;               // [512][64] Whh slice (stationary)
    float* As = sm + H_ * 64;     // [16][ASTRIDE] current h rows

    const int cta = blockIdx.x;
    const int mg  = cta >> 3;
    const int m0  = mg * 16;
    const int n0  = (cta & 7) * 64;
    const int t   = threadIdx.x;
    const int w   = t >> 5, l = t & 31;
    const int c   = 2 * l;
    const int r0  = 4 * w;

    // Load Whh[:, n0:n0+64] into smem once.
#pragma unroll 4
    for (int rep = 0; rep < 64; rep++) {
        int i4 = rep * 128 + t;
        int k  = i4 >> 4;
        int j4 = (i4 & 15) * 4;
        *(float4*)&Ws[k * 64 + j4] = *(const float4*)&Whh[(size_t)k * H_ + n0 + j4];
    }

    float2 ps0 = {0, 0}, ps1 = {0, 0}, ps2 = {0, 0}, ps3 = {0, 0};

    // prefetch P for step 0
    const size_t pstride = (size_t)B_ * H_;
    size_t pb = ((size_t)(m0 + r0)) * H_ + n0 + c;   // + step*pstride
    u64 p0 = *(const u64*)&g_P[pb];
    u64 p1 = *(const u64*)&g_P[pb + H_];
    u64 p2 = *(const u64*)&g_P[pb + 2 * H_];
    u64 p3 = *(const u64*)&g_P[pb + 3 * H_];

    unsigned* bar = &g_bars[mg];
    int cur = 0;
    for (int step = 0; step < S_; step++) {
        const float* hsrc = g_h[cur];
#pragma unroll
        for (int rep = 0; rep < 16; rep++) {
            int i4  = rep * 128 + t;
            int row = i4 >> 7;
            int k4  = (i4 & 127) * 4;
            *(float4*)&As[row * ASTRIDE + k4] =
                *(const float4*)&hsrc[(size_t)(m0 + row) * H_ + k4];
        }
        __syncthreads();

        u64 a0 = p0, a1 = p1, a2 = p2, a3 = p3;

        const float* ap0 = &As[(r0 + 0) * ASTRIDE];
        const float* ap1 = &As[(r0 + 1) * ASTRIDE];
        const float* ap2 = &As[(r0 + 2) * ASTRIDE];
        const float* ap3 = &As[(r0 + 3) * ASTRIDE];
#pragma unroll 4
        for (int k = 0; k < H_; k += 4) {
            float4 A0 = *(const float4*)(ap0 + k);
            float4 A1 = *(const float4*)(ap1 + k);
            float4 A2 = *(const float4*)(ap2 + k);
            float4 A3 = *(const float4*)(ap3 + k);
            const float* wp = &Ws[k * 64 + c];
            RK(x) RK(y) RK(z) RK(w)
        }

        float* hdst = g_h[cur ^ 1];
        const size_t ob = (size_t)(m0 + r0) * H_ + n0 + c;
        float2 v;
        v = u2f(a0); v.x = fmaxf(v.x, 0.f); v.y = fmaxf(v.y, 0.f);
        *(float2*)&hdst[ob]          = v; ps0.x += v.x; ps0.y += v.y;
        v = u2f(a1); v.x = fmaxf(v.x, 0.f); v.y = fmaxf(v.y, 0.f);
        *(float2*)&hdst[ob + H_]     = v; ps1.x += v.x; ps1.y += v.y;
        v = u2f(a2); v.x = fmaxf(v.x, 0.f); v.y = fmaxf(v.y, 0.f);
        *(float2*)&hdst[ob + 2 * H_] = v; ps2.x += v.x; ps2.y += v.y;
        v = u2f(a3); v.x = fmaxf(v.x, 0.f); v.y = fmaxf(v.y, 0.f);
        *(float2*)&hdst[ob + 3 * H_] = v; ps3.x += v.x; ps3.y += v.y;

        // prefetch next step's P (independent of the recurrence) BEFORE barrier
        if (step + 1 < S_) {
            const size_t pn = pb + (size_t)(step + 1) * pstride;
            p0 = *(const u64*)&g_P[pn];
            p1 = *(const u64*)&g_P[pn + H_];
            p2 = *(const u64*)&g_P[pn + 2 * H_];
            p3 = *(const u64*)&g_P[pn + 3 * H_];
        }

        if (step + 1 < S_) {
            __syncthreads();
            if (t == 0) {
                asm volatile("red.release.gpu.add.u32 [%0], 1;" :: "l"(bar) : "memory");
                unsigned v8, target = 8u * (unsigned)(step + 1);
                do {
                    asm volatile("ld.acquire.gpu.u32 %0, [%1];" : "=r"(v8) : "l"(bar) : "memory");
                } while (v8 < target);
            }
            __syncthreads();
        }
        cur ^= 1;
    }

    const float inv = 1.0f / (float)S_;
    const size_t ob = (size_t)(m0 + r0) * H_ + n0 + c;
    float2 q;
    q.x = ps0.x * inv; q.y = ps0.y * inv; *(float2*)&g_pool[ob]          = q;
    q.x = ps1.x * inv; q.y = ps1.y * inv; *(float2*)&g_pool[ob + H_]     = q;
    q.x = ps2.x * inv; q.y = ps2.y * inv; *(float2*)&g_pool[ob + 2 * H_] = q;
    q.x = ps3.x * inv; q.y = ps3.y * inv; *(float2*)&g_pool[ob + 3 * H_] = q;
}

// ============================================================================
// Kernel C: out = pooled @ Wfc + bfc
// ============================================================================
__global__ __launch_bounds__(128) void fc_kernel(const float* __restrict__ Wfc,
                                                 const float* __restrict__ bfc,
                                                 float* __restrict__ out)
{
    const int b = blockIdx.x;
    const int t = threadIdx.x;
    float s0 = 0, s1 = 0, s2 = 0, s3 = 0;
    const float* pr = &g_pool[(size_t)b * H_];
    for (int k = t; k < H_; k += 128) {
        float v = pr[k];
        float4 wv = *(const float4*)&Wfc[k * 4];
        s0 += v * wv.x; s1 += v * wv.y; s2 += v * wv.z; s3 += v * wv.w;
    }
#pragma unroll
    for (int o = 16; o > 0; o >>= 1) {
        s0 += __shfl_down_sync(0xffffffffu, s0, o);
        s1 += __shfl_down_sync(0xffffffffu, s1, o);
        s2 += __shfl_down_sync(0xffffffffu, s2, o);
        s3 += __shfl_down_sync(0xffffffffu, s3, o);
    }
    __shared__ float red[4][4];
    if ((t & 31) == 0) {
        int wrp = t >> 5;
        red[wrp][0] = s0; red[wrp][1] = s1; red[wrp][2] = s2; red[wrp][3] = s3;
    }
    __syncthreads();
    if (t < 4) {
        out[b * 4 + t] = red[0][t] + red[1][t] + red[2][t] + red[3][t] + bfc[t];
    }
}

// ============================================================================
extern "C" void kernel_launch(void* const* d_in, const int* in_sizes, int n_in,
                              void* d_out, int out_size)
{
    const int*   x   = (const int*)d_in[0];
    const float* emb = (const float*)d_in[1];
    const float* Wxh = (const float*)d_in[2];
    const float* bxh = (const float*)d_in[3];
    const float* Whh = (const float*)d_in[4];
    const float* bhh = (const float*)d_in[5];
    const float* Wfc = (const float*)d_in[6];
    const float* bfc = (const float*)d_in[7];
    float* out = (float*)d_out;

    void *hAddr = nullptr, *barAddr = nullptr;
    cudaGetSymbolAddress(&hAddr, g_h);
    cudaGetSymbolAddress(&barAddr, g_bars);
    cudaMemsetAsync(hAddr, 0, sizeof(float) * 2 * B_ * H_);
    cudaMemsetAsync(barAddr, 0, sizeof(unsigned) * 16);

    cudaFuncSetAttribute(precompute_kernel, cudaFuncAttributeMaxDynamicSharedMemorySize, PC_SMEM);
    cudaFuncSetAttribute(rnn_kernel, cudaFuncAttributeMaxDynamicSharedMemorySize, RNN_SMEM);

    precompute_kernel<<<dim3(4, 800), 256, PC_SMEM>>>(x, emb, Wxh, bxh, bhh);
    rnn_kernel<<<128, 128, RNN_SMEM>>>(Whh);
    fc_kernel<<<B_, 128>>>(Wfc, bfc, out);
}